// round 1
// baseline (speedup 1.0000x reference)
#include <cuda_runtime.h>
#include <stdint.h>

// =====================================================================
// EBSW loss: reproduce JAX threefry RNG + IMH chain + sliced W2 distances
// =====================================================================

#define PARTITIONABLE 1   // modern JAX default: jax_threefry_partitionable=True

static const int BATCH = 64;
static const int NPTS  = 4096;
static const int DIMS  = 3;
static const int LPROJ = 128;

__device__ float g_theta[LPROJ][BATCH][DIMS]; // normalized candidate thetas per step
__device__ float g_logu [LPROJ][BATCH];       // log(uniform) for acceptance, rows 1..127
__device__ float g_dist [BATCH][LPROJ];       // cand_dist[b][l]

// ---------------------------------------------------------------------
// threefry2x32 (20 rounds), exactly as JAX/Random123
// ---------------------------------------------------------------------
__device__ __forceinline__ uint2 tf2x32(unsigned k0, unsigned k1,
                                        unsigned x0, unsigned x1) {
    unsigned ks2 = k0 ^ k1 ^ 0x1BD11BDAu;
    x0 += k0; x1 += k1;
#define TFR(r) { x0 += x1; x1 = (x1 << (r)) | (x1 >> (32 - (r))); x1 ^= x0; }
    TFR(13) TFR(15) TFR(26) TFR(6)
    x0 += k1; x1 += ks2 + 1u;
    TFR(17) TFR(29) TFR(16) TFR(24)
    x0 += ks2; x1 += k0 + 2u;
    TFR(13) TFR(15) TFR(26) TFR(6)
    x0 += k0; x1 += k1 + 3u;
    TFR(17) TFR(29) TFR(16) TFR(24)
    x0 += k1; x1 += ks2 + 4u;
    TFR(13) TFR(15) TFR(26) TFR(6)
    x0 += ks2; x1 += k0 + 5u;
#undef TFR
    return make_uint2(x0, x1);
}

// ---------------------------------------------------------------------
// XLA ErfInv32 polynomial (Giles), op-ordering matched (no FMA contraction)
// ---------------------------------------------------------------------
__device__ __forceinline__ float xla_erfinv(float x) {
    float xx = __fmul_rn(x, x);
    float w  = -log1pf(-xx);
    float p;
    if (w < 5.0f) {
        w = __fadd_rn(w, -2.5f);
        p = 2.81022636e-08f;
        p = __fadd_rn( 3.43273939e-07f, __fmul_rn(p, w));
        p = __fadd_rn(-3.5233877e-06f,  __fmul_rn(p, w));
        p = __fadd_rn(-4.39150654e-06f, __fmul_rn(p, w));
        p = __fadd_rn( 0.00021858087f,  __fmul_rn(p, w));
        p = __fadd_rn(-0.00125372503f,  __fmul_rn(p, w));
        p = __fadd_rn(-0.00417768164f,  __fmul_rn(p, w));
        p = __fadd_rn( 0.246640727f,    __fmul_rn(p, w));
        p = __fadd_rn( 1.50140941f,     __fmul_rn(p, w));
    } else {
        w = __fadd_rn(__fsqrt_rn(w), -3.0f);
        p = -0.000200214257f;
        p = __fadd_rn( 0.000100950558f, __fmul_rn(p, w));
        p = __fadd_rn( 0.00134934322f,  __fmul_rn(p, w));
        p = __fadd_rn(-0.00367342844f,  __fmul_rn(p, w));
        p = __fadd_rn( 0.00573950773f,  __fmul_rn(p, w));
        p = __fadd_rn(-0.0076224613f,   __fmul_rn(p, w));
        p = __fadd_rn( 0.00943887047f,  __fmul_rn(p, w));
        p = __fadd_rn( 1.00167406f,     __fmul_rn(p, w));
        p = __fadd_rn( 2.83297682f,     __fmul_rn(p, w));
    }
    return __fmul_rn(p, x);
}

// bits -> float in [0,1): bitcast(bits>>9 | 0x3f800000) - 1   (exact ops)
__device__ __forceinline__ float bits_to_unit(unsigned bits) {
    return __uint_as_float((bits >> 9) | 0x3f800000u) - 1.0f;
}

// ---------------------------------------------------------------------
// RNG kernel: one block per chain step l. 192 threads.
//   key = (0, 42);  kl = fold_in(key, l) = TF(key, 0, l)
//   l==0: theta key = kl (no split). l>=1: ka, kb = split(kl)
//   theta_raw = sqrt(2)*erfinv(uniform(ka,(64,3),lo,1)); normalize over D
//   logu[l][b] = log(uniform(kb,(64,)))
// ---------------------------------------------------------------------
__global__ void ebsw_rng_kernel() {
    const int l = blockIdx.x;
    const int t = threadIdx.x;      // 0..191
    __shared__ float raw[BATCH * DIMS];

    uint2 kl = tf2x32(0u, 42u, 0u, (unsigned)l);
    uint2 ka, kb;
    if (l == 0) {
        ka = kl; kb = make_uint2(0u, 0u);
    } else {
#if PARTITIONABLE
        ka = tf2x32(kl.x, kl.y, 0u, 0u);
        kb = tf2x32(kl.x, kl.y, 0u, 1u);
#else
        uint2 p0 = tf2x32(kl.x, kl.y, 0u, 2u);
        uint2 p1 = tf2x32(kl.x, kl.y, 1u, 3u);
        ka = make_uint2(p0.x, p1.x);
        kb = make_uint2(p0.y, p1.y);
#endif
    }

    // normal bits for flat element t of shape (64,3)
    unsigned bits;
#if PARTITIONABLE
    { uint2 r = tf2x32(ka.x, ka.y, 0u, (unsigned)t); bits = r.x ^ r.y; }
#else
    if (t < 96) { uint2 r = tf2x32(ka.x, ka.y, (unsigned)t, (unsigned)(96 + t)); bits = r.x; }
    else        { uint2 r = tf2x32(ka.x, ka.y, (unsigned)(t - 96), (unsigned)t); bits = r.y; }
#endif
    const float LO = -0.99999994f;          // nextafterf(-1,0)
    float f = bits_to_unit(bits);
    float u = __fadd_rn(__fmul_rn(f, 2.0f), LO);  // (hi-lo) rounds to exactly 2.0f
    u = fmaxf(LO, u);
    raw[t] = __fmul_rn(1.41421356237309515f, xla_erfinv(u));
    __syncthreads();

    if (t < BATCH) {
        float v0 = raw[t * 3 + 0], v1 = raw[t * 3 + 1], v2 = raw[t * 3 + 2];
        float s  = __fadd_rn(__fadd_rn(__fmul_rn(v0, v0), __fmul_rn(v1, v1)),
                             __fmul_rn(v2, v2));
        float r  = __fsqrt_rn(s);
        g_theta[l][t][0] = __fdiv_rn(v0, r);
        g_theta[l][t][1] = __fdiv_rn(v1, r);
        g_theta[l][t][2] = __fdiv_rn(v2, r);

        if (l >= 1) {
            unsigned ub;
#if PARTITIONABLE
            { uint2 r2 = tf2x32(kb.x, kb.y, 0u, (unsigned)t); ub = r2.x ^ r2.y; }
#else
            if (t < 32) { uint2 r2 = tf2x32(kb.x, kb.y, (unsigned)t, (unsigned)(32 + t)); ub = r2.x; }
            else        { uint2 r2 = tf2x32(kb.x, kb.y, (unsigned)(t - 32), (unsigned)t); ub = r2.y; }
#endif
            g_logu[l][t] = logf(bits_to_unit(ub)); // minval=0,maxval=1 -> identity map
        }
    }
}

// ---------------------------------------------------------------------
// Distance kernel: one CTA per (b, l). Project, bitonic-sort xp & yp in
// shared memory (both arrays share each phase's barrier), reduce sum((dx)^2).
// ---------------------------------------------------------------------
static const int TPB = 512;

__global__ __launch_bounds__(TPB) void ebsw_dist_kernel(
        const float* __restrict__ x, const float* __restrict__ y) {
    __shared__ float s[2 * NPTS];     // [0,4096): xp, [4096,8192): yp
    const int blk = blockIdx.x;
    const int b = blk >> 7;
    const int l = blk & (LPROJ - 1);

    const float t0 = g_theta[l][b][0];
    const float t1 = g_theta[l][b][1];
    const float t2 = g_theta[l][b][2];
    const float* xb = x + (size_t)b * NPTS * DIMS;
    const float* yb = y + (size_t)b * NPTS * DIMS;

    for (int n = threadIdx.x; n < NPTS; n += TPB) {
        int o = n * 3;
        s[n]        = fmaf(xb[o], t0, fmaf(xb[o + 1], t1, xb[o + 2] * t2));
        s[NPTS + n] = fmaf(yb[o], t0, fmaf(yb[o + 1], t1, yb[o + 2] * t2));
    }
    __syncthreads();

    // bitonic sort of both halves simultaneously (2048 pairs per half)
    for (int k = 2; k <= NPTS; k <<= 1) {
        for (int j = k >> 1; j > 0; j >>= 1) {
            const int jm1 = j - 1;
#pragma unroll
            for (int w = 0; w < NPTS / TPB; ++w) {
                int t    = threadIdx.x + w * TPB;   // 0..4095
                int half = t >> 11;                 // which array
                int p    = t & 2047;                // pair index within array
                int i    = ((p & ~jm1) << 1) | (p & jm1);
                int idx  = (half << 12) + i;
                float a = s[idx], c = s[idx + j];
                bool up = ((i & k) == 0);
                if ((a > c) == up) { s[idx] = c; s[idx + j] = a; }
            }
            __syncthreads();
        }
    }

    // sum of squared rank-matched differences (fp64 accumulate)
    double acc = 0.0;
    for (int n = threadIdx.x; n < NPTS; n += TPB) {
        float d = s[n] - s[NPTS + n];
        acc += (double)d * (double)d;
    }
#pragma unroll
    for (int off = 16; off; off >>= 1)
        acc += __shfl_down_sync(0xffffffffu, acc, off);
    __shared__ double wsum[TPB / 32];
    if ((threadIdx.x & 31) == 0) wsum[threadIdx.x >> 5] = acc;
    __syncthreads();
    if (threadIdx.x < TPB / 32) {
        double v = wsum[threadIdx.x];
#pragma unroll
        for (int off = (TPB / 32) / 2; off; off >>= 1)
            v += __shfl_down_sync(0xffffu, v, off);
        if (threadIdx.x == 0) g_dist[b][l] = (float)v;
    }
}

// ---------------------------------------------------------------------
// Chain + loss kernel: serial IMH select per batch, then
// loss = mean_b sqrt(mean_l dist[b, sel[b,l]])
// ---------------------------------------------------------------------
__global__ void ebsw_chain_kernel(float* __restrict__ out) {
    const int b = threadIdx.x;      // 64 threads
    __shared__ double sh[BATCH];
    const float* db = g_dist[b];
    float dist_old = db[0];
    double acc = (double)dist_old;
    for (int l = 1; l < LPROJ; ++l) {
        float dn = db[l];
        float ar = fminf(0.0f, __fadd_rn(dn, -dist_old));
        if (g_logu[l][b] <= ar) dist_old = dn;   // accept
        acc += (double)dist_old;
    }
    sh[b] = sqrt(acc / (double)LPROJ);
    __syncthreads();
    if (b == 0) {
        double ssum = 0.0;
        for (int i = 0; i < BATCH; ++i) ssum += sh[i];
        out[0] = (float)(ssum / (double)BATCH);
    }
}

// ---------------------------------------------------------------------
extern "C" void kernel_launch(void* const* d_in, const int* in_sizes, int n_in,
                              void* d_out, int out_size) {
    const float* x = (const float*)d_in[0];
    const float* y = (const float*)d_in[1];
    float* out = (float*)d_out;

    ebsw_rng_kernel<<<LPROJ, BATCH * DIMS>>>();
    ebsw_dist_kernel<<<BATCH * LPROJ, TPB>>>(x, y);
    ebsw_chain_kernel<<<1, BATCH>>>(out);
}